// round 10
// baseline (speedup 1.0000x reference)
#include <cuda_runtime.h>
#include <math.h>

// Shapes fixed by the problem.
#define BB 16
#define SS 2048
#define DD 768
#define BSD (BB*SS*DD)

#define NBLK 296
#define NTHR 512
#define NWARP (NBLK*16)

// Scratch (no cudaMalloc allowed).
__device__ float2 g_dots[(size_t)BB*SS*3]; // per-row dots (hi,lo) with w0,w1,w2
__device__ double g_alpha[BB*SS];          // per-step alphas (fp64)
__device__ double g_A[BB*SS];              // per-batch inclusive prefix sums of alpha
__device__ int    g_seg[BB*SS];            // seg_end[k] = first t with A[t] >= k+1
__device__ float  g_weff[3*DD];            // fused conv+linear weights, layout [k*DD + i]
__device__ double g_beff;
__device__ unsigned g_bar[4];              // monotonic barrier counters (persist across replays)

// Grid-wide software barrier (296 co-resident blocks, 2/SM via launch_bounds).
// Monotonic counters; target rounds up to next multiple of NBLK — correct
// across serialized graph replays.
__device__ __forceinline__ void grid_sync(int slot) {
    __threadfence();
    __syncthreads();
    if (threadIdx.x == 0) {
        unsigned old = atomicAdd(&g_bar[slot], 1u);
        unsigned target = old - (old % NBLK) + NBLK;
        while (*((volatile unsigned*)&g_bar[slot]) < target)
            __nanosleep(64);
        __threadfence();
    }
    __syncthreads();
}

// Knuth TwoSum: exact error of fp32 add (6 FADD, fp32 pipe only).
__device__ __forceinline__ void two_sum(float a, float b, float& s, float& e) {
    s = a + b;
    float bb = s - a;
    e = (a - (s - bb)) + (b - bb);
}

__global__ void __launch_bounds__(NTHR, 2)
k_fused(const float* __restrict__ x, const int* __restrict__ lens,
        const float* __restrict__ conv_w, const float* __restrict__ conv_b,
        const float* __restrict__ lin_w, const float* __restrict__ lin_b,
        float* __restrict__ out, int out_size)
{
    __shared__ __align__(16) char shraw[10 * 1024];
    int tid  = threadIdx.x;
    int lane = tid & 31;
    int wid  = tid >> 5;                // 0..15
    int wg   = blockIdx.x * 16 + wid;   // global warp id

    // =====================================================================
    // Phase 1: fold Linear into Conv (fp32).  w_eff[k,i] = sum_o lin_w[o]*conv_w[o,i,k]
    // Sub-block of 256 threads: 32 columns x 8 o-parts; 72 tasks over 36 blocks.
    // =====================================================================
    {
        float* slw   = (float*)shraw;                        // [DD]  3KB
        float* spart = (float*)(shraw + 3072);               // [16][32] 2KB
        for (int i = tid; i < DD; i += NTHR) slw[i] = lin_w[i];
        __syncthreads();

        int sub   = tid >> 8;            // 0..1
        int t256  = tid & 255;
        int part  = t256 >> 5;           // 0..7
        int sl    = t256 & 31;
        int sb    = blockIdx.x * 2 + sub;
        if (sb < 72) {
            int c = sb * 32 + sl;        // column of conv_w (= i*3+k)
            float acc = 0.0f;
            int o0 = part * (DD/8);      // 96 o's per part
            #pragma unroll 2
            for (int o8 = o0; o8 < o0 + DD/8; o8 += 8) {
                float f = 0.0f;
                #pragma unroll
                for (int j = 0; j < 8; j++)
                    f = fmaf(slw[o8 + j], conv_w[(size_t)(o8 + j) * (3*DD) + c], f);
                acc += f;
            }
            spart[(sub*8 + part)*32 + sl] = acc;
        }
        __syncthreads();
        if (sb < 72 && part == 0) {
            int c = sb * 32 + sl;
            float s = 0.0f;
            #pragma unroll
            for (int p = 0; p < 8; p++) s += spart[(sub*8 + p)*32 + sl];
            int i = c / 3, k = c - 3*i;
            g_weff[k*DD + i] = s;
        }
        if (blockIdx.x == 0 && sub == 0 && part == 1) {   // bias (tiny fp64, one warp)
            double acc2 = 0.0;
            for (int o = sl; o < DD; o += 32)
                acc2 += (double)lin_w[o] * (double)conv_b[o];
            #pragma unroll
            for (int off = 16; off; off >>= 1)
                acc2 += __shfl_down_sync(0xffffffffu, acc2, off);
            if (sl == 0) g_beff = acc2 + (double)lin_b[0];
        }
    }
    grid_sync(0);

    // =====================================================================
    // Phase 2: per-row dots in df64 (fp32 pipe only). One row per warp.
    //   d_k[b,t] = dot(w_k, x[b,t,:]) for k=0,1,2; x read once.
    // =====================================================================
    {
        float4* sw = (float4*)shraw;     // [3*DD/4] 9KB
        for (int i = tid; i < 3*DD/4; i += NTHR)
            sw[i] = ((const float4*)g_weff)[i];
        __syncthreads();

        for (int r = wg; r < BB*SS; r += NWARP) {
            const float4* row = (const float4*)(x + (size_t)r * DD);
            float4 v[6];
            #pragma unroll
            for (int m = 0; m < 6; m++) v[m] = row[lane + 32*m];

            float s0 = 0.f, e0 = 0.f, s1 = 0.f, e1 = 0.f, s2 = 0.f, e2 = 0.f;
            #pragma unroll
            for (int m = 0; m < 6; m += 2) {            // chunks of 2 float4 = 8 floats
                float f0 = 0.f, f1 = 0.f, f2 = 0.f;
                #pragma unroll
                for (int mm = m; mm < m + 2; mm++) {
                    int idx = lane + 32 * mm;
                    float4 w0 = sw[idx];
                    float4 w1 = sw[DD/4 + idx];
                    float4 w2 = sw[2*(DD/4) + idx];
                    f0 = fmaf(w0.x, v[mm].x, fmaf(w0.y, v[mm].y, fmaf(w0.z, v[mm].z, fmaf(w0.w, v[mm].w, f0))));
                    f1 = fmaf(w1.x, v[mm].x, fmaf(w1.y, v[mm].y, fmaf(w1.z, v[mm].z, fmaf(w1.w, v[mm].w, f1))));
                    f2 = fmaf(w2.x, v[mm].x, fmaf(w2.y, v[mm].y, fmaf(w2.z, v[mm].z, fmaf(w2.w, v[mm].w, f2))));
                }
                float err;
                two_sum(s0, f0, s0, err); e0 += err;
                two_sum(s1, f1, s1, err); e1 += err;
                two_sum(s2, f2, s2, err); e2 += err;
            }
            // compensated warp reduction
            #pragma unroll
            for (int off = 16; off; off >>= 1) {
                float t0 = __shfl_down_sync(0xffffffffu, s0, off);
                float u0 = __shfl_down_sync(0xffffffffu, e0, off);
                float t1 = __shfl_down_sync(0xffffffffu, s1, off);
                float u1 = __shfl_down_sync(0xffffffffu, e1, off);
                float t2 = __shfl_down_sync(0xffffffffu, s2, off);
                float u2 = __shfl_down_sync(0xffffffffu, e2, off);
                float err;
                two_sum(s0, t0, s0, err); e0 = e0 + u0 + err;
                two_sum(s1, t1, s1, err); e1 = e1 + u1 + err;
                two_sum(s2, t2, s2, err); e2 = e2 + u2 + err;
            }
            if (lane == 0) {
                float2* o = g_dots + (size_t)r * 3;
                o[0] = make_float2(s0, e0);
                o[1] = make_float2(s1, e1);
                o[2] = make_float2(s2, e2);
            }
        }
    }
    grid_sync(1);

    // =====================================================================
    // Phase 2b: alphas, distributed over ALL blocks.
    //   logit[s] = b_eff + d0[s-1] + d1[s] + d2[s+1]
    // =====================================================================
    {
        double beff = g_beff;
        int gtid = blockIdx.x * NTHR + tid;
        for (int s = gtid; s < BB*SS; s += NBLK*NTHR) {
            int b   = s >> 11;
            int sin = s & (SS - 1);
            const float2* d = g_dots + (size_t)s * 3;
            float2 d1 = d[1];
            double z = beff + (double)d1.x + (double)d1.y;
            if (sin > 0)    { float2 d0 = d[-3]; z += (double)d0.x + (double)d0.y; }
            if (sin < SS-1) { float2 d2 = d[5];  z += (double)d2.x + (double)d2.y; }
            g_alpha[s] = (sin < lens[b]) ? (1.0 / (1.0 + exp(-z))) : 0.0;
        }
    }
    grid_sync(2);

    // =====================================================================
    // Phase 3: per-batch prefix sum (fp64 adds only) + segment index (blocks 0-15).
    // 512 threads x 4 consecutive elems. Detection compares STORED values only.
    // =====================================================================
    if (blockIdx.x < BB) {
        double* swarp = (double*)shraw;                  // [16]
        double* sincl = (double*)(shraw + 128);          // [512] 4KB
        int b = blockIdx.x;

        double a0v = g_alpha[b*SS + 4*tid];
        double a1v = g_alpha[b*SS + 4*tid + 1];
        double a2v = g_alpha[b*SS + 4*tid + 2];
        double a3v = g_alpha[b*SS + 4*tid + 3];
        double psum = ((a0v + a1v) + a2v) + a3v;

        double sc = psum;
        #pragma unroll
        for (int off = 1; off < 32; off <<= 1) {
            double tmp = __shfl_up_sync(0xffffffffu, sc, off);
            if (lane >= off) sc += tmp;
        }
        if (lane == 31) swarp[wid] = sc;
        __syncthreads();
        if (wid == 0 && lane < 16) {
            double v = swarp[lane];
            #pragma unroll
            for (int off = 1; off < 16; off <<= 1) {
                double tmp = __shfl_up_sync(0x0000ffffu, v, off);
                if (lane >= off) v += tmp;
            }
            swarp[lane] = v;
        }
        __syncthreads();

        double base = (wid > 0) ? swarp[wid - 1] : 0.0;
        double A3 = base + sc;          // stored A[4*tid+3]
        double A2 = A3 - a3v;           // stored A[4*tid+2]
        double A1 = A2 - a2v;           // stored A[4*tid+1]
        double A0 = A1 - a1v;           // stored A[4*tid]
        double* Ag = g_A + b*SS + 4*tid;
        Ag[0] = A0; Ag[1] = A1; Ag[2] = A2; Ag[3] = A3;
        sincl[tid] = A3;
        __syncthreads();

        double Am1 = (tid > 0) ? sincl[tid - 1] : 0.0;
        int f_m1 = (int)floor(Am1);
        int f0   = (int)floor(A0);
        int f1   = (int)floor(A1);
        int f2   = (int)floor(A2);
        int f3   = (int)floor(A3);
        int segb = b*SS;
        if (f0 > f_m1) g_seg[segb + (f0 - 1)] = 4*tid;
        if (f1 > f0)   g_seg[segb + (f1 - 1)] = 4*tid + 1;
        if (f2 > f1)   g_seg[segb + (f2 - 1)] = 4*tid + 2;
        if (f3 > f2)   g_seg[segb + (f3 - 1)] = 4*tid + 3;

        if (tid == NTHR - 1) {
            if (BSD + b < out_size) out[BSD + b] = (float)f3;
        }
    }
    grid_sync(3);

    // =====================================================================
    // Phase 4: gather output rows. One (b,k) per warp, warp-stride.
    //   k >= n -> zeros;  k < n -> c_k over t in [seg[k-1], seg[k]]
    // =====================================================================
    for (int task = wg; task < BB*SS; task += NWARP) {
        int b = task >> 11;
        int k = task & (SS - 1);

        const double* A = g_A + (size_t)b * SS;
        int n = (int)floor(A[SS - 1]);

        float4* orow = (float4*)(out + (size_t)task * DD);

        if (k >= n) {
            float4 z = make_float4(0.f, 0.f, 0.f, 0.f);
            #pragma unroll
            for (int j = 0; j < DD/128; j++) orow[lane + 32*j] = z;
            continue;
        }

        int t_start = (k > 0) ? g_seg[b*SS + k - 1] : 0;
        int t_end   = g_seg[b*SS + k];

        double kd = (double)k, kp1 = kd + 1.0;

        float4 acc[DD/128];
        #pragma unroll
        for (int j = 0; j < DD/128; j++) acc[j] = make_float4(0.f, 0.f, 0.f, 0.f);

        double Ap = (t_start > 0) ? A[t_start - 1] : 0.0;
        const float4* xb = (const float4*)(x + (size_t)b * SS * DD);

        for (int t = t_start; t <= t_end; t++) {
            double At = A[t];
            float w = (float)(fmin(At, kp1) - fmax(Ap, kd));
            Ap = At;
            const float4* row = xb + (size_t)t * (DD/4);
            #pragma unroll
            for (int j = 0; j < DD/128; j++) {
                float4 v = row[lane + 32*j];
                acc[j].x = fmaf(w, v.x, acc[j].x);
                acc[j].y = fmaf(w, v.y, acc[j].y);
                acc[j].z = fmaf(w, v.z, acc[j].z);
                acc[j].w = fmaf(w, v.w, acc[j].w);
            }
        }
        #pragma unroll
        for (int j = 0; j < DD/128; j++) orow[lane + 32*j] = acc[j];
    }
}

// ---------------------------------------------------------------------------
extern "C" void kernel_launch(void* const* d_in, const int* in_sizes, int n_in,
                              void* d_out, int out_size)
{
    const float* x      = (const float*)d_in[0];   // (B,S,D)
    const int*   lens   = (const int*)  d_in[1];   // (B,)
    const float* conv_w = (const float*)d_in[2];   // (D,D,3)
    const float* conv_b = (const float*)d_in[3];   // (D,)
    const float* lin_w  = (const float*)d_in[4];   // (1,D)
    const float* lin_b  = (const float*)d_in[5];   // (1,)
    float* out = (float*)d_out;

    k_fused<<<NBLK, NTHR>>>(x, lens, conv_w, conv_b, lin_w, lin_b, out, out_size);
}

// round 11
// speedup vs baseline: 1.1978x; 1.1978x over previous
#include <cuda_runtime.h>
#include <math.h>

// Shapes fixed by the problem.
#define BB 16
#define SS 2048
#define DD 768
#define BSD (BB*SS*DD)

#define NBLK 148
#define NTHR 1024
#define NWARP (NBLK*32)

// Scratch (no cudaMalloc allowed).
__device__ float2 g_dots[(size_t)BB*SS*3]; // per-row dots (hi,lo) with w0,w1,w2
__device__ double g_alpha[BB*SS];          // per-step alphas (fp64)
__device__ double g_A[BB*SS];              // per-batch inclusive prefix sums of alpha
__device__ int    g_seg[BB*SS];            // seg_end[k] = first t with A[t] >= k+1
__device__ float  g_weff[3*DD];            // fused conv+linear weights, layout [k*DD + i]
__device__ double g_beff;
__device__ unsigned g_bar[4];              // monotonic barrier counters (persist across replays)

// Grid-wide software barrier (148 co-resident blocks, 1/SM). Monotonic counters;
// target rounds up to next multiple of NBLK — correct across serialized replays.
__device__ __forceinline__ void grid_sync(int slot) {
    __threadfence();
    __syncthreads();
    if (threadIdx.x == 0) {
        unsigned old = atomicAdd(&g_bar[slot], 1u);
        unsigned target = old - (old % NBLK) + NBLK;
        while (*((volatile unsigned*)&g_bar[slot]) < target)
            __nanosleep(64);
        __threadfence();
    }
    __syncthreads();
}

// Knuth TwoSum: exact error of fp32 add (6 FADD, fp32 pipe only).
__device__ __forceinline__ void two_sum(float a, float b, float& s, float& e) {
    s = a + b;
    float bb = s - a;
    e = (a - (s - bb)) + (b - bb);
}

__global__ void __launch_bounds__(NTHR, 1)
k_fused(const float* __restrict__ x, const int* __restrict__ lens,
        const float* __restrict__ conv_w, const float* __restrict__ conv_b,
        const float* __restrict__ lin_w, const float* __restrict__ lin_b,
        float* __restrict__ out, int out_size)
{
    __shared__ __align__(16) char shraw[12 * 1024];
    int tid  = threadIdx.x;
    int lane = tid & 31;
    int wid  = tid >> 5;
    int wg   = blockIdx.x * 32 + wid;   // global warp id

    // =====================================================================
    // Phase 1: fold Linear into Conv (fp32).  w_eff[k,i] = sum_o lin_w[o]*conv_w[o,i,k]
    // Sub-block of 256 threads: 32 columns x 8 o-parts.
    // =====================================================================
    {
        float* slw   = (float*)shraw;                        // [DD]  3KB
        float* spart = (float*)(shraw + 3072);               // [32][32] 4KB
        for (int i = tid; i < DD; i += NTHR) slw[i] = lin_w[i];
        __syncthreads();

        int sub   = tid >> 8;            // 0..3
        int t256  = tid & 255;
        int part  = t256 >> 5;           // 0..7
        int sl    = t256 & 31;
        int sb    = blockIdx.x * 4 + sub;
        if (sb < 72) {
            int c = sb * 32 + sl;        // column of conv_w (= i*3+k)
            float acc = 0.0f;
            int o0 = part * (DD/8);      // 96 o's per part
            #pragma unroll 2
            for (int o8 = o0; o8 < o0 + DD/8; o8 += 8) {
                float f = 0.0f;
                #pragma unroll
                for (int j = 0; j < 8; j++)
                    f = fmaf(slw[o8 + j], conv_w[(size_t)(o8 + j) * (3*DD) + c], f);
                acc += f;
            }
            spart[(sub*8 + part)*32 + sl] = acc;
        }
        __syncthreads();
        if (sb < 72 && part == 0) {
            int c = sb * 32 + sl;
            float s = 0.0f;
            #pragma unroll
            for (int p = 0; p < 8; p++) s += spart[(sub*8 + p)*32 + sl];
            int i = c / 3, k = c - 3*i;
            g_weff[k*DD + i] = s;
        }
        if (blockIdx.x == 0 && sub == 0 && part == 1) {   // bias (tiny fp64, one warp)
            double acc2 = 0.0;
            for (int o = sl; o < DD; o += 32)
                acc2 += (double)lin_w[o] * (double)conv_b[o];
            #pragma unroll
            for (int off = 16; off; off >>= 1)
                acc2 += __shfl_down_sync(0xffffffffu, acc2, off);
            if (sl == 0) g_beff = acc2 + (double)lin_b[0];
        }
    }
    grid_sync(0);

    // =====================================================================
    // Phase 2: per-row dots in df64 (fp32 pipe only). One row per warp.
    //   d_k[b,t] = dot(w_k, x[b,t,:]) for k=0,1,2; x read once.
    // =====================================================================
    {
        float4* sw = (float4*)shraw;     // [3*DD/4] 9KB
        for (int i = tid; i < 3*DD/4; i += NTHR)
            sw[i] = ((const float4*)g_weff)[i];
        __syncthreads();

        for (int r = wg; r < BB*SS; r += NWARP) {
            const float4* row = (const float4*)(x + (size_t)r * DD);
            float4 v[6];
            #pragma unroll
            for (int m = 0; m < 6; m++) v[m] = row[lane + 32*m];

            float s0 = 0.f, e0 = 0.f, s1 = 0.f, e1 = 0.f, s2 = 0.f, e2 = 0.f;
            #pragma unroll
            for (int m = 0; m < 6; m += 2) {            // chunks of 2 float4 = 8 floats
                float f0 = 0.f, f1 = 0.f, f2 = 0.f;
                #pragma unroll
                for (int mm = m; mm < m + 2; mm++) {
                    int idx = lane + 32 * mm;
                    float4 w0 = sw[idx];
                    float4 w1 = sw[DD/4 + idx];
                    float4 w2 = sw[2*(DD/4) + idx];
                    f0 = fmaf(w0.x, v[mm].x, fmaf(w0.y, v[mm].y, fmaf(w0.z, v[mm].z, fmaf(w0.w, v[mm].w, f0))));
                    f1 = fmaf(w1.x, v[mm].x, fmaf(w1.y, v[mm].y, fmaf(w1.z, v[mm].z, fmaf(w1.w, v[mm].w, f1))));
                    f2 = fmaf(w2.x, v[mm].x, fmaf(w2.y, v[mm].y, fmaf(w2.z, v[mm].z, fmaf(w2.w, v[mm].w, f2))));
                }
                float err;
                two_sum(s0, f0, s0, err); e0 += err;
                two_sum(s1, f1, s1, err); e1 += err;
                two_sum(s2, f2, s2, err); e2 += err;
            }
            // compensated warp reduction
            #pragma unroll
            for (int off = 16; off; off >>= 1) {
                float t0 = __shfl_down_sync(0xffffffffu, s0, off);
                float u0 = __shfl_down_sync(0xffffffffu, e0, off);
                float t1 = __shfl_down_sync(0xffffffffu, s1, off);
                float u1 = __shfl_down_sync(0xffffffffu, e1, off);
                float t2 = __shfl_down_sync(0xffffffffu, s2, off);
                float u2 = __shfl_down_sync(0xffffffffu, e2, off);
                float err;
                two_sum(s0, t0, s0, err); e0 = e0 + u0 + err;
                two_sum(s1, t1, s1, err); e1 = e1 + u1 + err;
                two_sum(s2, t2, s2, err); e2 = e2 + u2 + err;
            }
            if (lane == 0) {
                float2* o = g_dots + (size_t)r * 3;
                o[0] = make_float2(s0, e0);
                o[1] = make_float2(s1, e1);
                o[2] = make_float2(s2, e2);
            }
        }
    }
    grid_sync(1);

    // =====================================================================
    // Phase 2b: alphas, distributed over ALL blocks.
    //   logit[s] = b_eff + d0[s-1] + d1[s] + d2[s+1]
    // =====================================================================
    {
        double beff = g_beff;
        int gtid = blockIdx.x * NTHR + tid;
        for (int s = gtid; s < BB*SS; s += NBLK*NTHR) {
            int b   = s >> 11;
            int sin = s & (SS - 1);
            const float2* d = g_dots + (size_t)s * 3;
            float2 d1 = d[1];
            double z = beff + (double)d1.x + (double)d1.y;
            if (sin > 0)    { float2 d0 = d[-3]; z += (double)d0.x + (double)d0.y; }
            if (sin < SS-1) { float2 d2 = d[5];  z += (double)d2.x + (double)d2.y; }
            g_alpha[s] = (sin < lens[b]) ? (1.0 / (1.0 + exp(-z))) : 0.0;
        }
    }
    grid_sync(2);

    // =====================================================================
    // Phase 3: per-batch prefix sum (fp64 adds only) + segment index (blocks 0-15).
    // =====================================================================
    if (blockIdx.x < BB) {
        double* swarp = (double*)shraw;                  // [32]
        double* sincl = (double*)(shraw + 256);          // [SS/2] 8KB
        int b = blockIdx.x;

        double a0v = g_alpha[b*SS + 2*tid];
        double a1v = g_alpha[b*SS + 2*tid + 1];
        double psum = a0v + a1v;

        #pragma unroll
        for (int off = 1; off < 32; off <<= 1) {
            double tmp = __shfl_up_sync(0xffffffffu, psum, off);
            if (lane >= off) psum += tmp;
        }
        if (lane == 31) swarp[wid] = psum;
        __syncthreads();
        if (wid == 0) {
            double v = swarp[lane];
            #pragma unroll
            for (int off = 1; off < 32; off <<= 1) {
                double tmp = __shfl_up_sync(0xffffffffu, v, off);
                if (lane >= off) v += tmp;
            }
            swarp[lane] = v;
        }
        __syncthreads();

        double base = (wid > 0) ? swarp[wid - 1] : 0.0;
        double incl = base + psum;             // A[2*tid + 1]
        double A0   = incl - a1v;              // A[2*tid]
        g_A[b*SS + 2*tid]     = A0;
        g_A[b*SS + 2*tid + 1] = incl;
        sincl[tid] = incl;
        __syncthreads();

        double Am1 = (tid > 0) ? sincl[tid - 1] : 0.0;
        int f_m1 = (int)floor(Am1);
        int f0   = (int)floor(A0);
        int f1   = (int)floor(incl);
        if (f0 > f_m1) g_seg[b*SS + (f0 - 1)] = 2*tid;
        if (f1 > f0)   g_seg[b*SS + (f1 - 1)] = 2*tid + 1;

        if (tid == SS/2 - 1) {
            if (BSD + b < out_size) out[BSD + b] = (float)f1;
        }
    }
    grid_sync(3);

    // =====================================================================
    // Phase 4: gather output rows. One (b,k) per warp, warp-stride.
    //   k >= n -> zeros;  k < n -> c_k = sum_t w_t * h_t,
    //     w_t = min(A_t,k+1) - max(A_{t-1},k),  t in [seg[k-1], seg[k]].
    // Weights computed LANE-PARALLEL in fp64 (chunks of 32 steps), then
    // broadcast via shfl — 32x fewer fp64-pipe ops, bitwise-identical w.
    // =====================================================================
    for (int task = wg; task < BB*SS; task += NWARP) {
        int b = task >> 11;
        int k = task & (SS - 1);

        const double* A = g_A + (size_t)b * SS;
        int n = (int)floor(A[SS - 1]);

        float4* orow = (float4*)(out + (size_t)task * DD);

        if (k >= n) {
            float4 z = make_float4(0.f, 0.f, 0.f, 0.f);
            #pragma unroll
            for (int j = 0; j < DD/128; j++) orow[lane + 32*j] = z;
            continue;
        }

        int t_start = (k > 0) ? g_seg[b*SS + k - 1] : 0;
        int t_end   = g_seg[b*SS + k];

        double kd = (double)k, kp1 = kd + 1.0;

        float4 acc[DD/128];
        #pragma unroll
        for (int j = 0; j < DD/128; j++) acc[j] = make_float4(0.f, 0.f, 0.f, 0.f);

        const float4* xb = (const float4*)(x + (size_t)b * SS * DD);

        for (int base = t_start; base <= t_end; base += 32) {
            int t = base + lane;
            float wlane = 0.0f;
            if (t <= t_end) {
                double Ap = (t > 0) ? A[t - 1] : 0.0;
                double At = A[t];
                wlane = (float)(fmin(At, kp1) - fmax(Ap, kd));
            }
            int cnt = min(32, t_end - base + 1);
            for (int j = 0; j < cnt; j++) {
                float w = __shfl_sync(0xffffffffu, wlane, j);
                const float4* row = xb + (size_t)(base + j) * (DD/4);
                #pragma unroll
                for (int q = 0; q < DD/128; q++) {
                    float4 v = row[lane + 32*q];
                    acc[q].x = fmaf(w, v.x, acc[q].x);
                    acc[q].y = fmaf(w, v.y, acc[q].y);
                    acc[q].z = fmaf(w, v.z, acc[q].z);
                    acc[q].w = fmaf(w, v.w, acc[q].w);
                }
            }
        }
        #pragma unroll
        for (int j = 0; j < DD/128; j++) orow[lane + 32*j] = acc[j];
    }
}

// ---------------------------------------------------------------------------
extern "C" void kernel_launch(void* const* d_in, const int* in_sizes, int n_in,
                              void* d_out, int out_size)
{
    const float* x      = (const float*)d_in[0];   // (B,S,D)
    const int*   lens   = (const int*)  d_in[1];   // (B,)
    const float* conv_w = (const float*)d_in[2];   // (D,D,3)
    const float* conv_b = (const float*)d_in[3];   // (D,)
    const float* lin_w  = (const float*)d_in[4];   // (1,D)
    const float* lin_b  = (const float*)d_in[5];   // (1,)
    float* out = (float*)d_out;

    k_fused<<<NBLK, NTHR>>>(x, lens, conv_w, conv_b, lin_w, lin_b, out, out_size);
}

// round 13
// speedup vs baseline: 1.4900x; 1.2440x over previous
#include <cuda_runtime.h>
#include <math.h>

// Shapes fixed by the problem.
#define BB 16
#define SS 2048
#define DD 768
#define BSD (BB*SS*DD)

#define NBLK 148
#define NTHR 1024
#define NWARP (NBLK*32)

// Scratch (no cudaMalloc allowed).
__device__ float2 g_dots[(size_t)BB*SS*3]; // per-row dots (hi,lo) with w0,w1,w2
__device__ double g_alpha[BB*SS];          // per-step alphas (fp64)
__device__ double g_A[BB*SS];              // per-batch inclusive prefix sums of alpha
__device__ int    g_seg[BB*SS];            // seg_end[k] = first t with A[t] >= k+1
__device__ float  g_weff[3*DD];            // fused conv+linear weights, layout [k*DD + i]
__device__ double g_beff;
__device__ unsigned g_bar[4];              // monotonic barrier counters (persist across replays)

// Grid-wide software barrier (148 co-resident blocks, 1/SM). Monotonic counters;
// target rounds up to next multiple of NBLK — correct across serialized replays.
__device__ __forceinline__ void grid_sync(int slot) {
    __threadfence();
    __syncthreads();
    if (threadIdx.x == 0) {
        unsigned old = atomicAdd(&g_bar[slot], 1u);
        unsigned target = old - (old % NBLK) + NBLK;
        while (*((volatile unsigned*)&g_bar[slot]) < target)
            __nanosleep(64);
        __threadfence();
    }
    __syncthreads();
}

// Knuth TwoSum: exact error of fp32 add (6 FADD, fp32 pipe only).
__device__ __forceinline__ void two_sum(float a, float b, float& s, float& e) {
    s = a + b;
    float bb = s - a;
    e = (a - (s - bb)) + (b - bb);
}

__global__ void __launch_bounds__(NTHR, 1)
k_fused(const float* __restrict__ x, const int* __restrict__ lens,
        const float* __restrict__ conv_w, const float* __restrict__ conv_b,
        const float* __restrict__ lin_w, const float* __restrict__ lin_b,
        float* __restrict__ out, int out_size)
{
    __shared__ __align__(16) char shraw[12 * 1024];
    int tid  = threadIdx.x;
    int lane = tid & 31;
    int wid  = tid >> 5;
    int wg   = blockIdx.x * 32 + wid;   // global warp id

    // =====================================================================
    // Phase 1: fold Linear into Conv (fp32).  w_eff[k,i] = sum_o lin_w[o]*conv_w[o,i,k]
    // Sub-block of 256 threads: 32 columns x 8 o-parts.
    // =====================================================================
    {
        float* slw   = (float*)shraw;                        // [DD]  3KB
        float* spart = (float*)(shraw + 3072);               // [32][32] 4KB
        for (int i = tid; i < DD; i += NTHR) slw[i] = lin_w[i];
        __syncthreads();

        int sub   = tid >> 8;            // 0..3
        int t256  = tid & 255;
        int part  = t256 >> 5;           // 0..7
        int sl    = t256 & 31;
        int sb    = blockIdx.x * 4 + sub;
        if (sb < 72) {
            int c = sb * 32 + sl;        // column of conv_w (= i*3+k)
            float acc = 0.0f;
            int o0 = part * (DD/8);      // 96 o's per part
            #pragma unroll 2
            for (int o8 = o0; o8 < o0 + DD/8; o8 += 8) {
                float f = 0.0f;
                #pragma unroll
                for (int j = 0; j < 8; j++)
                    f = fmaf(slw[o8 + j], conv_w[(size_t)(o8 + j) * (3*DD) + c], f);
                acc += f;
            }
            spart[(sub*8 + part)*32 + sl] = acc;
        }
        __syncthreads();
        if (sb < 72 && part == 0) {
            int c = sb * 32 + sl;
            float s = 0.0f;
            #pragma unroll
            for (int p = 0; p < 8; p++) s += spart[(sub*8 + p)*32 + sl];
            int i = c / 3, k = c - 3*i;
            g_weff[k*DD + i] = s;
        }
        if (blockIdx.x == 0 && sub == 0 && part == 1) {   // bias (tiny fp64, one warp)
            double acc2 = 0.0;
            for (int o = sl; o < DD; o += 32)
                acc2 += (double)lin_w[o] * (double)conv_b[o];
            #pragma unroll
            for (int off = 16; off; off >>= 1)
                acc2 += __shfl_down_sync(0xffffffffu, acc2, off);
            if (sl == 0) g_beff = acc2 + (double)lin_b[0];
        }
    }
    grid_sync(0);

    // =====================================================================
    // Phase 2: per-row dots in df64 (fp32 pipe only). One row per warp.
    //   d_k[b,t] = dot(w_k, x[b,t,:]) for k=0,1,2; x read once.
    // SKIP rows t > len[b]: alphas are masked past len, and logit[s] (s<len)
    // only consumes dot rows 0..len. ~Half the x-read traffic vanishes.
    // =====================================================================
    {
        float4* sw = (float4*)shraw;     // [3*DD/4] 9KB
        for (int i = tid; i < 3*DD/4; i += NTHR)
            sw[i] = ((const float4*)g_weff)[i];
        __syncthreads();

        for (int r = wg; r < BB*SS; r += NWARP) {
            int b   = r >> 11;
            int sin = r & (SS - 1);
            if (sin > __ldg(&lens[b])) continue;   // row never consumed

            const float4* row = (const float4*)(x + (size_t)r * DD);
            float4 v[6];
            #pragma unroll
            for (int m = 0; m < 6; m++) v[m] = row[lane + 32*m];

            float s0 = 0.f, e0 = 0.f, s1 = 0.f, e1 = 0.f, s2 = 0.f, e2 = 0.f;
            #pragma unroll
            for (int m = 0; m < 6; m += 2) {            // chunks of 2 float4 = 8 floats
                float f0 = 0.f, f1 = 0.f, f2 = 0.f;
                #pragma unroll
                for (int mm = m; mm < m + 2; mm++) {
                    int idx = lane + 32 * mm;
                    float4 w0 = sw[idx];
                    float4 w1 = sw[DD/4 + idx];
                    float4 w2 = sw[2*(DD/4) + idx];
                    f0 = fmaf(w0.x, v[mm].x, fmaf(w0.y, v[mm].y, fmaf(w0.z, v[mm].z, fmaf(w0.w, v[mm].w, f0))));
                    f1 = fmaf(w1.x, v[mm].x, fmaf(w1.y, v[mm].y, fmaf(w1.z, v[mm].z, fmaf(w1.w, v[mm].w, f1))));
                    f2 = fmaf(w2.x, v[mm].x, fmaf(w2.y, v[mm].y, fmaf(w2.z, v[mm].z, fmaf(w2.w, v[mm].w, f2))));
                }
                float err;
                two_sum(s0, f0, s0, err); e0 += err;
                two_sum(s1, f1, s1, err); e1 += err;
                two_sum(s2, f2, s2, err); e2 += err;
            }
            // compensated warp reduction
            #pragma unroll
            for (int off = 16; off; off >>= 1) {
                float t0 = __shfl_down_sync(0xffffffffu, s0, off);
                float u0 = __shfl_down_sync(0xffffffffu, e0, off);
                float t1 = __shfl_down_sync(0xffffffffu, s1, off);
                float u1 = __shfl_down_sync(0xffffffffu, e1, off);
                float t2 = __shfl_down_sync(0xffffffffu, s2, off);
                float u2 = __shfl_down_sync(0xffffffffu, e2, off);
                float err;
                two_sum(s0, t0, s0, err); e0 = e0 + u0 + err;
                two_sum(s1, t1, s1, err); e1 = e1 + u1 + err;
                two_sum(s2, t2, s2, err); e2 = e2 + u2 + err;
            }
            if (lane == 0) {
                float2* o = g_dots + (size_t)r * 3;
                o[0] = make_float2(s0, e0);
                o[1] = make_float2(s1, e1);
                o[2] = make_float2(s2, e2);
            }
        }
    }
    grid_sync(1);

    // =====================================================================
    // Phase 2b: alphas, distributed over ALL blocks.
    //   logit[s] = b_eff + d0[s-1] + d1[s] + d2[s+1];  s >= len -> 0 (no loads)
    // =====================================================================
    {
        double beff = g_beff;
        int gtid = blockIdx.x * NTHR + tid;
        for (int s = gtid; s < BB*SS; s += NBLK*NTHR) {
            int b   = s >> 11;
            int sin = s & (SS - 1);
            if (sin >= __ldg(&lens[b])) { g_alpha[s] = 0.0; continue; }
            const float2* d = g_dots + (size_t)s * 3;
            float2 d1 = d[1];
            double z = beff + (double)d1.x + (double)d1.y;
            if (sin > 0)    { float2 d0 = d[-3]; z += (double)d0.x + (double)d0.y; }
            if (sin < SS-1) { float2 d2 = d[5];  z += (double)d2.x + (double)d2.y; }
            g_alpha[s] = 1.0 / (1.0 + exp(-z));
        }
    }
    grid_sync(2);

    // =====================================================================
    // Phase 3: per-batch prefix sum (fp64 adds only) + segment index (blocks 0-15).
    // =====================================================================
    if (blockIdx.x < BB) {
        double* swarp = (double*)shraw;                  // [32]
        double* sincl = (double*)(shraw + 256);          // [SS/2] 8KB
        int b = blockIdx.x;

        double a0v = g_alpha[b*SS + 2*tid];
        double a1v = g_alpha[b*SS + 2*tid + 1];
        double psum = a0v + a1v;

        #pragma unroll
        for (int off = 1; off < 32; off <<= 1) {
            double tmp = __shfl_up_sync(0xffffffffu, psum, off);
            if (lane >= off) psum += tmp;
        }
        if (lane == 31) swarp[wid] = psum;
        __syncthreads();
        if (wid == 0) {
            double v = swarp[lane];
            #pragma unroll
            for (int off = 1; off < 32; off <<= 1) {
                double tmp = __shfl_up_sync(0xffffffffu, v, off);
                if (lane >= off) v += tmp;
            }
            swarp[lane] = v;
        }
        __syncthreads();

        double base = (wid > 0) ? swarp[wid - 1] : 0.0;
        double incl = base + psum;             // A[2*tid + 1]
        double A0   = incl - a1v;              // A[2*tid]
        g_A[b*SS + 2*tid]     = A0;
        g_A[b*SS + 2*tid + 1] = incl;
        sincl[tid] = incl;
        __syncthreads();

        double Am1 = (tid > 0) ? sincl[tid - 1] : 0.0;
        int f_m1 = (int)floor(Am1);
        int f0   = (int)floor(A0);
        int f1   = (int)floor(incl);
        if (f0 > f_m1) g_seg[b*SS + (f0 - 1)] = 2*tid;
        if (f1 > f0)   g_seg[b*SS + (f1 - 1)] = 2*tid + 1;

        if (tid == SS/2 - 1) {
            if (BSD + b < out_size) out[BSD + b] = (float)f1;
        }
    }
    grid_sync(3);

    // =====================================================================
    // Phase 4: gather output rows. One (b,k) per warp, warp-stride.
    //   k >= n -> zeros;  k < n -> c_k = sum_t w_t * h_t,
    //     w_t = min(A_t,k+1) - max(A_{t-1},k),  t in [seg[k-1], seg[k]].
    // Weights computed lane-parallel in fp64, broadcast via shfl.
    // =====================================================================
    for (int task = wg; task < BB*SS; task += NWARP) {
        int b = task >> 11;
        int k = task & (SS - 1);

        const double* A = g_A + (size_t)b * SS;
        int n = (int)floor(A[SS - 1]);

        float4* orow = (float4*)(out + (size_t)task * DD);

        if (k >= n) {
            float4 z = make_float4(0.f, 0.f, 0.f, 0.f);
            #pragma unroll
            for (int j = 0; j < DD/128; j++) orow[lane + 32*j] = z;
            continue;
        }

        int t_start = (k > 0) ? g_seg[b*SS + k - 1] : 0;
        int t_end   = g_seg[b*SS + k];

        double kd = (double)k, kp1 = kd + 1.0;

        float4 acc[DD/128];
        #pragma unroll
        for (int j = 0; j < DD/128; j++) acc[j] = make_float4(0.f, 0.f, 0.f, 0.f);

        const float4* xb = (const float4*)(x + (size_t)b * SS * DD);

        for (int base = t_start; base <= t_end; base += 32) {
            int t = base + lane;
            float wlane = 0.0f;
            if (t <= t_end) {
                double Ap = (t > 0) ? A[t - 1] : 0.0;
                double At = A[t];
                wlane = (float)(fmin(At, kp1) - fmax(Ap, kd));
            }
            int cnt = min(32, t_end - base + 1);
            for (int j = 0; j < cnt; j++) {
                float w = __shfl_sync(0xffffffffu, wlane, j);
                const float4* row = xb + (size_t)(base + j) * (DD/4);
                #pragma unroll
                for (int q = 0; q < DD/128; q++) {
                    float4 v = row[lane + 32*q];
                    acc[q].x = fmaf(w, v.x, acc[q].x);
                    acc[q].y = fmaf(w, v.y, acc[q].y);
                    acc[q].z = fmaf(w, v.z, acc[q].z);
                    acc[q].w = fmaf(w, v.w, acc[q].w);
                }
            }
        }
        #pragma unroll
        for (int j = 0; j < DD/128; j++) orow[lane + 32*j] = acc[j];
    }
}

// ---------------------------------------------------------------------------
extern "C" void kernel_launch(void* const* d_in, const int* in_sizes, int n_in,
                              void* d_out, int out_size)
{
    const float* x      = (const float*)d_in[0];   // (B,S,D)
    const int*   lens   = (const int*)  d_in[1];   // (B,)
    const float* conv_w = (const float*)d_in[2];   // (D,D,3)
    const float* conv_b = (const float*)d_in[3];   // (D,)
    const float* lin_w  = (const float*)d_in[4];   // (1,D)
    const float* lin_b  = (const float*)d_in[5];   // (1,)
    float* out = (float*)d_out;

    k_fused<<<NBLK, NTHR>>>(x, lens, conv_w, conv_b, lin_w, lin_b, out, out_size);
}

// round 14
// speedup vs baseline: 1.5449x; 1.0368x over previous
#include <cuda_runtime.h>
#include <math.h>

// Shapes fixed by the problem.
#define BB 16
#define SS 2048
#define DD 768
#define BSD (BB*SS*DD)

#define NBLK 148
#define NTHR 1024
#define NWARP (NBLK*32)

// Scratch (no cudaMalloc allowed).
__device__ float2 g_dots[(size_t)BB*SS*3]; // per-row dots (hi,lo) with w0,w1,w2
__device__ double g_alpha[BB*SS];          // per-step alphas (fp64)
__device__ double g_A[BB*SS];              // per-batch inclusive prefix sums of alpha
__device__ int    g_seg[BB*SS];            // seg_end[k] = first t with A[t] >= k+1
__device__ float  g_weff[3*DD];            // fused conv+linear weights, layout [k*DD + i]
__device__ double g_beff;
__device__ unsigned g_bar[4];              // monotonic barrier counters (persist across replays)

// Grid-wide software barrier (148 co-resident blocks, 1/SM). Monotonic counters;
// target rounds up to next multiple of NBLK — correct across serialized replays.
__device__ __forceinline__ void grid_sync(int slot) {
    __threadfence();
    __syncthreads();
    if (threadIdx.x == 0) {
        unsigned old = atomicAdd(&g_bar[slot], 1u);
        unsigned target = old - (old % NBLK) + NBLK;
        while (*((volatile unsigned*)&g_bar[slot]) < target)
            __nanosleep(64);
        __threadfence();
    }
    __syncthreads();
}

// Knuth TwoSum: exact error of fp32 add (6 FADD, fp32 pipe only).
__device__ __forceinline__ void two_sum(float a, float b, float& s, float& e) {
    s = a + b;
    float bb = s - a;
    e = (a - (s - bb)) + (b - bb);
}

__global__ void __launch_bounds__(NTHR, 1)
k_fused(const float* __restrict__ x, const int* __restrict__ lens,
        const float* __restrict__ conv_w, const float* __restrict__ conv_b,
        const float* __restrict__ lin_w, const float* __restrict__ lin_b,
        float* __restrict__ out, int out_size)
{
    __shared__ __align__(16) char shraw[12 * 1024];
    int tid  = threadIdx.x;
    int lane = tid & 31;
    int wid  = tid >> 5;
    int wg   = blockIdx.x * 32 + wid;   // global warp id

    // =====================================================================
    // Phase 1: fold Linear into Conv (fp32).  w_eff[k,i] = sum_o lin_w[o]*conv_w[o,i,k]
    // Sub-block of 256 threads: 32 columns x 8 o-parts.
    // =====================================================================
    {
        float* slw   = (float*)shraw;                        // [DD]  3KB
        float* spart = (float*)(shraw + 3072);               // [32][32] 4KB
        for (int i = tid; i < DD; i += NTHR) slw[i] = lin_w[i];
        __syncthreads();

        int sub   = tid >> 8;            // 0..3
        int t256  = tid & 255;
        int part  = t256 >> 5;           // 0..7
        int sl    = t256 & 31;
        int sb    = blockIdx.x * 4 + sub;
        if (sb < 72) {
            int c = sb * 32 + sl;        // column of conv_w (= i*3+k)
            float acc = 0.0f;
            int o0 = part * (DD/8);      // 96 o's per part
            #pragma unroll 2
            for (int o8 = o0; o8 < o0 + DD/8; o8 += 8) {
                float f = 0.0f;
                #pragma unroll
                for (int j = 0; j < 8; j++)
                    f = fmaf(slw[o8 + j], conv_w[(size_t)(o8 + j) * (3*DD) + c], f);
                acc += f;
            }
            spart[(sub*8 + part)*32 + sl] = acc;
        }
        __syncthreads();
        if (sb < 72 && part == 0) {
            int c = sb * 32 + sl;
            float s = 0.0f;
            #pragma unroll
            for (int p = 0; p < 8; p++) s += spart[(sub*8 + p)*32 + sl];
            int i = c / 3, k = c - 3*i;
            g_weff[k*DD + i] = s;
        }
        if (blockIdx.x == 0 && sub == 0 && part == 1) {   // bias (tiny fp64, one warp)
            double acc2 = 0.0;
            for (int o = sl; o < DD; o += 32)
                acc2 += (double)lin_w[o] * (double)conv_b[o];
            #pragma unroll
            for (int off = 16; off; off >>= 1)
                acc2 += __shfl_down_sync(0xffffffffu, acc2, off);
            if (sl == 0) g_beff = acc2 + (double)lin_b[0];
        }
    }
    grid_sync(0);

    // =====================================================================
    // Phase 2: per-row dots in df64 (fp32 pipe only). One row per warp.
    //   d_k[b,t] = dot(w_k, x[b,t,:]) for k=0,1,2; x read once.
    // SKIP rows t > len[b] (never consumed).
    // THEN: zero-write all output rows k >= len[b] — provably zero
    // (alpha<1 => A[last] < len => n <= len-1), independent of the scan.
    // These stores ride in the latency shadow of the dots loads.
    // =====================================================================
    {
        float4* sw = (float4*)shraw;     // [3*DD/4] 9KB
        for (int i = tid; i < 3*DD/4; i += NTHR)
            sw[i] = ((const float4*)g_weff)[i];
        __syncthreads();

        for (int r = wg; r < BB*SS; r += NWARP) {
            int b   = r >> 11;
            int sin = r & (SS - 1);
            if (sin > __ldg(&lens[b])) continue;   // row never consumed

            const float4* row = (const float4*)(x + (size_t)r * DD);
            float4 v[6];
            #pragma unroll
            for (int m = 0; m < 6; m++) v[m] = row[lane + 32*m];

            float s0 = 0.f, e0 = 0.f, s1 = 0.f, e1 = 0.f, s2 = 0.f, e2 = 0.f;
            #pragma unroll
            for (int m = 0; m < 6; m += 2) {            // chunks of 2 float4 = 8 floats
                float f0 = 0.f, f1 = 0.f, f2 = 0.f;
                #pragma unroll
                for (int mm = m; mm < m + 2; mm++) {
                    int idx = lane + 32 * mm;
                    float4 w0 = sw[idx];
                    float4 w1 = sw[DD/4 + idx];
                    float4 w2 = sw[2*(DD/4) + idx];
                    f0 = fmaf(w0.x, v[mm].x, fmaf(w0.y, v[mm].y, fmaf(w0.z, v[mm].z, fmaf(w0.w, v[mm].w, f0))));
                    f1 = fmaf(w1.x, v[mm].x, fmaf(w1.y, v[mm].y, fmaf(w1.z, v[mm].z, fmaf(w1.w, v[mm].w, f1))));
                    f2 = fmaf(w2.x, v[mm].x, fmaf(w2.y, v[mm].y, fmaf(w2.z, v[mm].z, fmaf(w2.w, v[mm].w, f2))));
                }
                float err;
                two_sum(s0, f0, s0, err); e0 += err;
                two_sum(s1, f1, s1, err); e1 += err;
                two_sum(s2, f2, s2, err); e2 += err;
            }
            // compensated warp reduction
            #pragma unroll
            for (int off = 16; off; off >>= 1) {
                float t0 = __shfl_down_sync(0xffffffffu, s0, off);
                float u0 = __shfl_down_sync(0xffffffffu, e0, off);
                float t1 = __shfl_down_sync(0xffffffffu, s1, off);
                float u1 = __shfl_down_sync(0xffffffffu, e1, off);
                float t2 = __shfl_down_sync(0xffffffffu, s2, off);
                float u2 = __shfl_down_sync(0xffffffffu, e2, off);
                float err;
                two_sum(s0, t0, s0, err); e0 = e0 + u0 + err;
                two_sum(s1, t1, s1, err); e1 = e1 + u1 + err;
                two_sum(s2, t2, s2, err); e2 = e2 + u2 + err;
            }
            if (lane == 0) {
                float2* o = g_dots + (size_t)r * 3;
                o[0] = make_float2(s0, e0);
                o[1] = make_float2(s1, e1);
                o[2] = make_float2(s2, e2);
            }
        }

        // Early zero-writes: rows k >= len[b] (no scan dependence).
        float4 z = make_float4(0.f, 0.f, 0.f, 0.f);
        for (int task = wg; task < BB*SS; task += NWARP) {
            int b = task >> 11;
            int k = task & (SS - 1);
            if (k < __ldg(&lens[b])) continue;
            float4* orow = (float4*)(out + (size_t)task * DD);
            #pragma unroll
            for (int j = 0; j < DD/128; j++) orow[lane + 32*j] = z;
        }
    }
    grid_sync(1);

    // =====================================================================
    // Phase 2b: alphas, distributed over ALL blocks.
    //   logit[s] = b_eff + d0[s-1] + d1[s] + d2[s+1];  s >= len -> 0 (no loads)
    // =====================================================================
    {
        double beff = g_beff;
        int gtid = blockIdx.x * NTHR + tid;
        for (int s = gtid; s < BB*SS; s += NBLK*NTHR) {
            int b   = s >> 11;
            int sin = s & (SS - 1);
            if (sin >= __ldg(&lens[b])) { g_alpha[s] = 0.0; continue; }
            const float2* d = g_dots + (size_t)s * 3;
            float2 d1 = d[1];
            double z = beff + (double)d1.x + (double)d1.y;
            if (sin > 0)    { float2 d0 = d[-3]; z += (double)d0.x + (double)d0.y; }
            if (sin < SS-1) { float2 d2 = d[5];  z += (double)d2.x + (double)d2.y; }
            g_alpha[s] = 1.0 / (1.0 + exp(-z));
        }
    }
    grid_sync(2);

    // =====================================================================
    // Phase 3: per-batch prefix sum (fp64 adds only) + segment index (blocks 0-15).
    // =====================================================================
    if (blockIdx.x < BB) {
        double* swarp = (double*)shraw;                  // [32]
        double* sincl = (double*)(shraw + 256);          // [SS/2] 8KB
        int b = blockIdx.x;

        double a0v = g_alpha[b*SS + 2*tid];
        double a1v = g_alpha[b*SS + 2*tid + 1];
        double psum = a0v + a1v;

        #pragma unroll
        for (int off = 1; off < 32; off <<= 1) {
            double tmp = __shfl_up_sync(0xffffffffu, psum, off);
            if (lane >= off) psum += tmp;
        }
        if (lane == 31) swarp[wid] = psum;
        __syncthreads();
        if (wid == 0) {
            double v = swarp[lane];
            #pragma unroll
            for (int off = 1; off < 32; off <<= 1) {
                double tmp = __shfl_up_sync(0xffffffffu, v, off);
                if (lane >= off) v += tmp;
            }
            swarp[lane] = v;
        }
        __syncthreads();

        double base = (wid > 0) ? swarp[wid - 1] : 0.0;
        double incl = base + psum;             // A[2*tid + 1]
        double A0   = incl - a1v;              // A[2*tid]
        g_A[b*SS + 2*tid]     = A0;
        g_A[b*SS + 2*tid + 1] = incl;
        sincl[tid] = incl;
        __syncthreads();

        double Am1 = (tid > 0) ? sincl[tid - 1] : 0.0;
        int f_m1 = (int)floor(Am1);
        int f0   = (int)floor(A0);
        int f1   = (int)floor(incl);
        if (f0 > f_m1) g_seg[b*SS + (f0 - 1)] = 2*tid;
        if (f1 > f0)   g_seg[b*SS + (f1 - 1)] = 2*tid + 1;

        if (tid == SS/2 - 1) {
            if (BSD + b < out_size) out[BSD + b] = (float)f1;
        }
    }
    grid_sync(3);

    // =====================================================================
    // Phase 4: gather output rows. One (b,k) per warp, warp-stride.
    //   k >= len  -> already zeroed in phase 2, skip.
    //   n <= k < len -> zeros;  k < n -> c_k = sum_t w_t * h_t,
    //     w_t = min(A_t,k+1) - max(A_{t-1},k),  t in [seg[k-1], seg[k]].
    // Weights computed lane-parallel in fp64, broadcast via shfl.
    // =====================================================================
    for (int task = wg; task < BB*SS; task += NWARP) {
        int b = task >> 11;
        int k = task & (SS - 1);
        if (k >= __ldg(&lens[b])) continue;    // zeroed in phase 2

        const double* A = g_A + (size_t)b * SS;
        int n = (int)floor(A[SS - 1]);

        float4* orow = (float4*)(out + (size_t)task * DD);

        if (k >= n) {
            float4 z = make_float4(0.f, 0.f, 0.f, 0.f);
            #pragma unroll
            for (int j = 0; j < DD/128; j++) orow[lane + 32*j] = z;
            continue;
        }

        int t_start = (k > 0) ? g_seg[b*SS + k - 1] : 0;
        int t_end   = g_seg[b*SS + k];

        double kd = (double)k, kp1 = kd + 1.0;

        float4 acc[DD/128];
        #pragma unroll
        for (int j = 0; j < DD/128; j++) acc[j] = make_float4(0.f, 0.f, 0.f, 0.f);

        const float4* xb = (const float4*)(x + (size_t)b * SS * DD);

        for (int base = t_start; base <= t_end; base += 32) {
            int t = base + lane;
            float wlane = 0.0f;
            if (t <= t_end) {
                double Ap = (t > 0) ? A[t - 1] : 0.0;
                double At = A[t];
                wlane = (float)(fmin(At, kp1) - fmax(Ap, kd));
            }
            int cnt = min(32, t_end - base + 1);
            for (int j = 0; j < cnt; j++) {
                float w = __shfl_sync(0xffffffffu, wlane, j);
                const float4* row = xb + (size_t)(base + j) * (DD/4);
                #pragma unroll
                for (int q = 0; q < DD/128; q++) {
                    float4 v = row[lane + 32*q];
                    acc[q].x = fmaf(w, v.x, acc[q].x);
                    acc[q].y = fmaf(w, v.y, acc[q].y);
                    acc[q].z = fmaf(w, v.z, acc[q].z);
                    acc[q].w = fmaf(w, v.w, acc[q].w);
                }
            }
        }
        #pragma unroll
        for (int j = 0; j < DD/128; j++) orow[lane + 32*j] = acc[j];
    }
}

// ---------------------------------------------------------------------------
extern "C" void kernel_launch(void* const* d_in, const int* in_sizes, int n_in,
                              void* d_out, int out_size)
{
    const float* x      = (const float*)d_in[0];   // (B,S,D)
    const int*   lens   = (const int*)  d_in[1];   // (B,)
    const float* conv_w = (const float*)d_in[2];   // (D,D,3)
    const float* conv_b = (const float*)d_in[3];   // (D,)
    const float* lin_w  = (const float*)d_in[4];   // (1,D)
    const float* lin_b  = (const float*)d_in[5];   // (1,)
    float* out = (float*)d_out;

    k_fused<<<NBLK, NTHR>>>(x, lens, conv_w, conv_b, lin_w, lin_b, out, out_size);
}